// round 5
// baseline (speedup 1.0000x reference)
#include <cuda_runtime.h>

// Problem dims  (V, E, H, N, L = 32000, 512, 1024, 16, 128)
#define VV 32000
#define NB 16            // batch
#define LL 128           // seq len
#define EE 512           // embed dim  (!!)
#define HH 1024          // hidden dim
#define G4 4096          // 4*H
#define MM (NB*LL)       // 2048 rows in the big GEMMs

// Scratch (static device allocs are the sanctioned scratch mechanism).
__device__ __align__(16) float g_X0[(size_t)MM * G4];   // 33.5 MB
__device__ __align__(16) float g_X1[(size_t)MM * G4];   // 33.5 MB
__device__ __align__(16) float g_H0[(size_t)MM * HH];   //  8.4 MB
__device__ __align__(16) float g_hbuf[NB * HH];         // h state, [b][k]
__device__ __align__(16) float g_c[NB * HH];            // c state, [b][j]

__device__ __forceinline__ float sigf(float x) { return 1.0f / (1.0f + __expf(-x)); }

// ---------------------------------------------------------------------------
// C[m][r] = sum_k A[m][k] * B[r][k] + bias[r];  A gathered via tokens if set.
// K is the contraction dim AND the row stride of A and B (both contiguous).
// Tile 128x128, 256 threads, 8x8 per thread, K-tile 16. Static smem only.
// ---------------------------------------------------------------------------
template <int K>
__global__ __launch_bounds__(256) void gemm_nt(
    const float* __restrict__ Aext,
    const int*   __restrict__ tokens,
    const float* __restrict__ B,
    const float* __restrict__ bias,
    int a_sel, int c_sel)
{
    __shared__ __align__(16) float As[16][132];
    __shared__ __align__(16) float Bs[16][132];

    float* C = c_sel ? g_X1 : g_X0;
    const int bm = blockIdx.y, br = blockIdx.x;
    const int tid = threadIdx.x;
    const int tx = tid & 15, ty = tid >> 4;

    const int r0 = tid >> 2;          // 0..63
    const int r1 = r0 + 64;           // 64..127
    const int kq = (tid & 3) << 2;    // 0,4,8,12

    const float* arow0;
    const float* arow1;
    if (tokens) {
        int gm0 = bm * 128 + r0, gm1 = bm * 128 + r1;
        int t0 = tokens[(gm0 & (NB - 1)) * LL + (gm0 >> 4)];
        int t1 = tokens[(gm1 & (NB - 1)) * LL + (gm1 >> 4)];
        t0 = min(max(t0, 0), VV - 1);   // fault-proof
        t1 = min(max(t1, 0), VV - 1);
        arow0 = Aext + (size_t)t0 * K;
        arow1 = Aext + (size_t)t1 * K;
    } else {
        const float* A = a_sel ? g_H0 : Aext;
        arow0 = A + (size_t)(bm * 128 + r0) * K;
        arow1 = A + (size_t)(bm * 128 + r1) * K;
    }
    const float* brow0 = B + (size_t)(br * 128 + r0) * K;
    const float* brow1 = B + (size_t)(br * 128 + r1) * K;

    float acc[8][8];
#pragma unroll
    for (int i = 0; i < 8; i++)
#pragma unroll
        for (int jj = 0; jj < 8; jj++) acc[i][jj] = 0.0f;

    for (int k0 = 0; k0 < K; k0 += 16) {
        float4 av0 = *(const float4*)(arow0 + k0 + kq);
        float4 av1 = *(const float4*)(arow1 + k0 + kq);
        float4 bv0 = *(const float4*)(brow0 + k0 + kq);
        float4 bv1 = *(const float4*)(brow1 + k0 + kq);
        As[kq + 0][r0] = av0.x; As[kq + 1][r0] = av0.y; As[kq + 2][r0] = av0.z; As[kq + 3][r0] = av0.w;
        As[kq + 0][r1] = av1.x; As[kq + 1][r1] = av1.y; As[kq + 2][r1] = av1.z; As[kq + 3][r1] = av1.w;
        Bs[kq + 0][r0] = bv0.x; Bs[kq + 1][r0] = bv0.y; Bs[kq + 2][r0] = bv0.z; Bs[kq + 3][r0] = bv0.w;
        Bs[kq + 0][r1] = bv1.x; Bs[kq + 1][r1] = bv1.y; Bs[kq + 2][r1] = bv1.z; Bs[kq + 3][r1] = bv1.w;
        __syncthreads();

#pragma unroll
        for (int kk = 0; kk < 16; kk++) {
            float4 a0 = *(const float4*)&As[kk][ty * 8];
            float4 a1 = *(const float4*)&As[kk][ty * 8 + 4];
            float4 b0 = *(const float4*)&Bs[kk][tx * 8];
            float4 b1 = *(const float4*)&Bs[kk][tx * 8 + 4];
            float a[8] = {a0.x, a0.y, a0.z, a0.w, a1.x, a1.y, a1.z, a1.w};
            float b[8] = {b0.x, b0.y, b0.z, b0.w, b1.x, b1.y, b1.z, b1.w};
#pragma unroll
            for (int i = 0; i < 8; i++)
#pragma unroll
                for (int jj = 0; jj < 8; jj++)
                    acc[i][jj] = fmaf(a[i], b[jj], acc[i][jj]);
        }
        __syncthreads();
    }

    const int gc = br * 128 + tx * 8;
    float bia[8];
#pragma unroll
    for (int jj = 0; jj < 8; jj++) bia[jj] = bias[gc + jj];
#pragma unroll
    for (int i = 0; i < 8; i++) {
        int gm = bm * 128 + ty * 8 + i;
        float4 o0, o1;
        o0.x = acc[i][0] + bia[0]; o0.y = acc[i][1] + bia[1];
        o0.z = acc[i][2] + bia[2]; o0.w = acc[i][3] + bia[3];
        o1.x = acc[i][4] + bia[4]; o1.y = acc[i][5] + bia[5];
        o1.z = acc[i][6] + bia[6]; o1.w = acc[i][7] + bia[7];
        *(float4*)(C + (size_t)gm * G4 + gc)     = o0;
        *(float4*)(C + (size_t)gm * G4 + gc + 4) = o1;
    }
}

// ---------------------------------------------------------------------------
// ONE LSTM timestep (launched LL times per layer; kernel boundary = fence).
// Grid = 128 CTAs x 256 threads. Warp w owns h-column j = blk*8 + w:
// its 4 gate rows x 16 batches, K=1024 split over lanes.
// h staged in smem in two 512-wide halves (static smem ~34 KB).
// ---------------------------------------------------------------------------
__global__ __launch_bounds__(256) void lstm_step(
    const float* __restrict__ Whh,
    float* __restrict__ Out,
    int t, int xsel, int mode)
{
    __shared__ __align__(16) float hs[NB][512];
    __shared__ float gs[8][64];

    const float* Xg = xsel ? g_X1 : g_X0;
    const int tid = threadIdx.x, lane = tid & 31, w = tid >> 5;
    const int j = blockIdx.x * 8 + w;

    float acc[4][16];
#pragma unroll
    for (int g = 0; g < 4; g++)
#pragma unroll
        for (int b = 0; b < 16; b++) acc[g][b] = 0.0f;

    for (int half = 0; half < 2; half++) {
        if (t == 0) {
            for (int i = tid; i < NB * 512 / 4; i += 256)
                ((float4*)&hs[0][0])[i] = make_float4(0.f, 0.f, 0.f, 0.f);
        } else {
            for (int i = tid; i < NB * 512 / 4; i += 256) {
                int b = i >> 7, c4 = i & 127;
                ((float4*)&hs[0][0])[i] =
                    ((const float4*)g_hbuf)[b * (HH / 4) + half * 128 + c4];
            }
        }
        __syncthreads();

        const float* w0 = Whh + (size_t)(0 * HH + j) * HH + half * 512;
        const float* w1 = Whh + (size_t)(1 * HH + j) * HH + half * 512;
        const float* w2 = Whh + (size_t)(2 * HH + j) * HH + half * 512;
        const float* w3 = Whh + (size_t)(3 * HH + j) * HH + half * 512;

        for (int kk = 0; kk < 512; kk += 128) {
            const int k = kk + lane * 4;
            float4 wv0 = *(const float4*)(w0 + k);
            float4 wv1 = *(const float4*)(w1 + k);
            float4 wv2 = *(const float4*)(w2 + k);
            float4 wv3 = *(const float4*)(w3 + k);
#pragma unroll
            for (int b = 0; b < 16; b++) {
                float4 hv = *(const float4*)(&hs[b][k]);
                acc[0][b] += wv0.x * hv.x + wv0.y * hv.y + wv0.z * hv.z + wv0.w * hv.w;
                acc[1][b] += wv1.x * hv.x + wv1.y * hv.y + wv1.z * hv.z + wv1.w * hv.w;
                acc[2][b] += wv2.x * hv.x + wv2.y * hv.y + wv2.z * hv.z + wv2.w * hv.w;
                acc[3][b] += wv3.x * hv.x + wv3.y * hv.y + wv3.z * hv.z + wv3.w * hv.w;
            }
        }
        __syncthreads();
    }

#pragma unroll
    for (int g = 0; g < 4; g++)
#pragma unroll
        for (int b = 0; b < 16; b++) {
            float v = acc[g][b];
            v += __shfl_xor_sync(0xffffffffu, v, 16);
            v += __shfl_xor_sync(0xffffffffu, v, 8);
            v += __shfl_xor_sync(0xffffffffu, v, 4);
            v += __shfl_xor_sync(0xffffffffu, v, 2);
            v += __shfl_xor_sync(0xffffffffu, v, 1);
            acc[g][b] = v;
        }
    if (lane == 0) {
#pragma unroll
        for (int g = 0; g < 4; g++)
#pragma unroll
            for (int b = 0; b < 16; b++) gs[w][g * 16 + b] = acc[g][b];
    }
    __syncwarp();

    if (lane < 16) {
        const int b = lane;
        const float* xr = Xg + (size_t)(t * NB + b) * G4 + j;
        float gi = gs[w][ 0 + b] + xr[0];
        float gf = gs[w][16 + b] + xr[HH];
        float gg = gs[w][32 + b] + xr[2 * HH];
        float go = gs[w][48 + b] + xr[3 * HH];
        float cprev = (t == 0) ? 0.0f : g_c[b * HH + j];
        float c = sigf(gf) * cprev + sigf(gi) * tanhf(gg);
        float h = sigf(go) * tanhf(c);
        g_c[b * HH + j] = c;
        g_hbuf[b * HH + j] = h;
        if (mode == 0)
            g_H0[(size_t)(t * NB + b) * HH + j] = h;
        else
            Out[(size_t)b * (LL * HH) + (size_t)t * HH + j] = h;
    }
}

// ---------------------------------------------------------------------------
extern "C" void kernel_launch(void* const* d_in, const int* in_sizes, int n_in,
                              void* d_out, int out_size)
{
    // Identify inputs by element count (now unambiguous):
    //   x: 2048 | emb: 32000*512 | w_ih0: 4096*512 (unique)
    //   4096*1024 x3 in order: w_hh0, w_ih1, w_hh1 | 4096 x2: b0, b1
    const int*   x    = nullptr;
    const float* emb  = nullptr;
    const float* wih0 = nullptr;
    const float* bias_[2] = {nullptr, nullptr};
    const float* w4[3] = {nullptr, nullptr, nullptr};
    int nbias = 0, nw = 0;
    for (int i = 0; i < n_in; i++) {
        long long sz = in_sizes[i];
        if (sz == (long long)NB * LL)             x = (const int*)d_in[i];
        else if (sz == (long long)VV * EE)        emb = (const float*)d_in[i];
        else if (sz == (long long)G4 * EE)        wih0 = (const float*)d_in[i];
        else if (sz == (long long)G4)             { if (nbias < 2) bias_[nbias++] = (const float*)d_in[i]; }
        else if (sz == (long long)G4 * HH)        { if (nw < 3) w4[nw++] = (const float*)d_in[i]; }
    }
    if (!x || !emb || !wih0 || nbias < 2 || nw < 3) {   // positional fallback
        x = (const int*)d_in[0];
        emb = (const float*)d_in[1];
        wih0 = (const float*)d_in[2];
        w4[0] = (const float*)d_in[3];
        bias_[0] = (const float*)d_in[4];
        w4[1] = (const float*)d_in[5];
        w4[2] = (const float*)d_in[6];
        bias_[1] = (const float*)d_in[7];
    }
    const float* whh0 = w4[0];
    const float* b0   = bias_[0];
    const float* wih1 = w4[1];
    const float* whh1 = w4[2];
    const float* b1   = bias_[1];
    float* out = (float*)d_out;

    dim3 ggrid(G4 / 128, MM / 128);  // (32, 16)

    // Phase 1: X0 = emb[x] @ w_ih0^T + b0   (K = E = 512)
    gemm_nt<EE><<<ggrid, 256>>>(emb, x, wih0, b0, 0, 0);
    // Phase 2: layer-0 recurrence, one launch per step -> g_H0
    for (int t = 0; t < LL; t++)
        lstm_step<<<128, 256>>>(whh0, out, t, 0, 0);
    // Phase 3: X1 = H0 @ w_ih1^T + b1       (K = H = 1024)
    gemm_nt<HH><<<ggrid, 256>>>(emb, nullptr, wih1, b1, 1, 1);
    // Phase 4: layer-1 recurrence -> out [N][L][H]
    for (int t = 0; t < LL; t++)
        lstm_step<<<128, 256>>>(whh1, out, t, 1, 1);
}

// round 6
// speedup vs baseline: 1.3228x; 1.3228x over previous
#include <cuda_runtime.h>

// Problem dims  (V, E, H, N, L = 32000, 512, 1024, 16, 128)
#define VV 32000
#define NB 16
#define LL 128
#define EE 512
#define HH 1024
#define G4 4096
#define MM (NB*LL)
#define RB 128           // persistent recurrence CTAs (1/SM, co-resident)

// Scratch
__device__ __align__(16) float g_X0[(size_t)MM * G4];   // 33.5 MB
__device__ __align__(16) float g_X1[(size_t)MM * G4];   // 33.5 MB
__device__ __align__(16) float g_H0[(size_t)MM * HH];   //  8.4 MB
__device__ __align__(16) float g_h[2][NB * HH];         // h double buffer, [k][b]
__device__ unsigned g_bar_arrive = 0;
__device__ unsigned g_bar_gen    = 0;

__device__ __forceinline__ float sigf(float x) { return 1.0f / (1.0f + __expf(-x)); }

// ---- packed f32x2 helpers -------------------------------------------------
typedef unsigned long long ull;

__device__ __forceinline__ ull pack2(float x) {
    ull r; asm("mov.b64 %0, {%1, %1};" : "=l"(r) : "f"(x)); return r;
}
__device__ __forceinline__ void ffma2(ull& d, ull a, ull b) {
    asm("fma.rn.f32x2 %0, %1, %2, %0;" : "+l"(d) : "l"(a), "l"(b));
}
__device__ __forceinline__ ull fadd2(ull a, ull b) {
    ull d; asm("add.rn.f32x2 %0, %1, %2;" : "=l"(d) : "l"(a), "l"(b)); return d;
}
__device__ __forceinline__ void unpack2(ull v, float& lo, float& hi) {
    asm("mov.b64 {%0, %1}, %2;" : "=f"(lo), "=f"(hi) : "l"(v));
}

// ---- grid-wide barrier (all RB CTAs co-resident) --------------------------
__device__ __forceinline__ void grid_sync() {
    __threadfence();
    __syncthreads();
    if (threadIdx.x == 0) {
        unsigned gen = ((volatile unsigned*)&g_bar_gen)[0];
        unsigned a = atomicAdd(&g_bar_arrive, 1u);
        if (a == RB - 1) {
            g_bar_arrive = 0;
            __threadfence();
            atomicExch(&g_bar_gen, gen + 1u);
        } else {
            while (((volatile unsigned*)&g_bar_gen)[0] == gen) { }
        }
        __threadfence();
    }
    __syncthreads();
}

// ---------------------------------------------------------------------------
// GEMM  C[m][r] = sum_k A[m][k]*B[r][k] + bias[r];  A gathered via tokens.
// ---------------------------------------------------------------------------
template <int K>
__global__ __launch_bounds__(256) void gemm_nt(
    const float* __restrict__ Aext,
    const int*   __restrict__ tokens,
    const float* __restrict__ B,
    const float* __restrict__ bias,
    int a_sel, int c_sel)
{
    __shared__ __align__(16) float As[16][132];
    __shared__ __align__(16) float Bs[16][132];

    float* C = c_sel ? g_X1 : g_X0;
    const int bm = blockIdx.y, br = blockIdx.x;
    const int tid = threadIdx.x;
    const int tx = tid & 15, ty = tid >> 4;

    const int r0 = tid >> 2;
    const int r1 = r0 + 64;
    const int kq = (tid & 3) << 2;

    const float* arow0;
    const float* arow1;
    if (tokens) {
        int gm0 = bm * 128 + r0, gm1 = bm * 128 + r1;
        int t0 = tokens[(gm0 & (NB - 1)) * LL + (gm0 >> 4)];
        int t1 = tokens[(gm1 & (NB - 1)) * LL + (gm1 >> 4)];
        t0 = min(max(t0, 0), VV - 1);
        t1 = min(max(t1, 0), VV - 1);
        arow0 = Aext + (size_t)t0 * K;
        arow1 = Aext + (size_t)t1 * K;
    } else {
        const float* A = a_sel ? g_H0 : Aext;
        arow0 = A + (size_t)(bm * 128 + r0) * K;
        arow1 = A + (size_t)(bm * 128 + r1) * K;
    }
    const float* brow0 = B + (size_t)(br * 128 + r0) * K;
    const float* brow1 = B + (size_t)(br * 128 + r1) * K;

    float acc[8][8];
#pragma unroll
    for (int i = 0; i < 8; i++)
#pragma unroll
        for (int jj = 0; jj < 8; jj++) acc[i][jj] = 0.0f;

    for (int k0 = 0; k0 < K; k0 += 16) {
        float4 av0 = *(const float4*)(arow0 + k0 + kq);
        float4 av1 = *(const float4*)(arow1 + k0 + kq);
        float4 bv0 = *(const float4*)(brow0 + k0 + kq);
        float4 bv1 = *(const float4*)(brow1 + k0 + kq);
        As[kq + 0][r0] = av0.x; As[kq + 1][r0] = av0.y; As[kq + 2][r0] = av0.z; As[kq + 3][r0] = av0.w;
        As[kq + 0][r1] = av1.x; As[kq + 1][r1] = av1.y; As[kq + 2][r1] = av1.z; As[kq + 3][r1] = av1.w;
        Bs[kq + 0][r0] = bv0.x; Bs[kq + 1][r0] = bv0.y; Bs[kq + 2][r0] = bv0.z; Bs[kq + 3][r0] = bv0.w;
        Bs[kq + 0][r1] = bv1.x; Bs[kq + 1][r1] = bv1.y; Bs[kq + 2][r1] = bv1.z; Bs[kq + 3][r1] = bv1.w;
        __syncthreads();

#pragma unroll
        for (int kk = 0; kk < 16; kk++) {
            float4 a0 = *(const float4*)&As[kk][ty * 8];
            float4 a1 = *(const float4*)&As[kk][ty * 8 + 4];
            float4 b0 = *(const float4*)&Bs[kk][tx * 8];
            float4 b1 = *(const float4*)&Bs[kk][tx * 8 + 4];
            float a[8] = {a0.x, a0.y, a0.z, a0.w, a1.x, a1.y, a1.z, a1.w};
            float b[8] = {b0.x, b0.y, b0.z, b0.w, b1.x, b1.y, b1.z, b1.w};
#pragma unroll
            for (int i = 0; i < 8; i++)
#pragma unroll
                for (int jj = 0; jj < 8; jj++)
                    acc[i][jj] = fmaf(a[i], b[jj], acc[i][jj]);
        }
        __syncthreads();
    }

    const int gc = br * 128 + tx * 8;
    float bia[8];
#pragma unroll
    for (int jj = 0; jj < 8; jj++) bia[jj] = bias[gc + jj];
#pragma unroll
    for (int i = 0; i < 8; i++) {
        int gm = bm * 128 + ty * 8 + i;
        float4 o0, o1;
        o0.x = acc[i][0] + bia[0]; o0.y = acc[i][1] + bia[1];
        o0.z = acc[i][2] + bia[2]; o0.w = acc[i][3] + bia[3];
        o1.x = acc[i][4] + bia[4]; o1.y = acc[i][5] + bia[5];
        o1.z = acc[i][6] + bia[6]; o1.w = acc[i][7] + bia[7];
        *(float4*)(C + (size_t)gm * G4 + gc)     = o0;
        *(float4*)(C + (size_t)gm * G4 + gc + 4) = o1;
    }
}

// ---------------------------------------------------------------------------
// Persistent LSTM recurrence: 128 CTAs x 256 thr, all 128 steps in one launch.
// Warp w owns column j = blk*8 + w (4 gate rows x 16 batches).
// smem: ws[8][4][1024] weights (loaded once) | hs[1024][20] padded h |
//       gs[8][64] reduced gates | xs[8][4][16] staged X slice.
// h round-trips through L2 double buffer g_h[2] ([k][b] layout).
// c lives in registers (lane<16). Packed f32x2 math throughout.
// ---------------------------------------------------------------------------
__global__ __launch_bounds__(256) void lstm_rec(
    const float* __restrict__ Whh,
    float* __restrict__ Out,
    int xsel, int mode)
{
    extern __shared__ __align__(16) float sm[];
    float* ws = sm;                    // 32768 floats
    float* hs = sm + 32768;            // 20480 floats (1024 rows x 20)
    float* gs = hs + 20480;            // 512
    float* xs = gs + 512;              // 512

    const float* Xg = xsel ? g_X1 : g_X0;
    const int tid = threadIdx.x, lane = tid & 31, wp = tid >> 5;
    const int j = blockIdx.x * 8 + wp;

    // ---- preload weight slice (128 KB) into smem, layout ws[w][g][k] ----
    for (int i = tid; i < 8192; i += 256) {
        int wgk = i * 4;
        int w_ = wgk >> 12, g = (wgk >> 10) & 3, k = wgk & 1023;
        ((float4*)ws)[i] = *(const float4*)(Whh + (size_t)(g * HH + blockIdx.x * 8 + w_) * HH + k);
    }
    // zero hs (t=0 state), pads included
    for (int i = tid; i < 20480; i += 256) hs[i] = 0.0f;

    float creg = 0.0f;   // c state (lane<16)
    __syncthreads();

    for (int t = 0; t < LL; t++) {
        if (t > 0) {
            // stage h from L2 double buffer into padded smem [k][20]
            const float4* src = (const float4*)g_h[t & 1];
            for (int i = tid; i < 4096; i += 256) {
                float4 hv = __ldcg(src + i);
                int k = i >> 2, b4 = (i & 3) << 2;
                *(float4*)(hs + k * 20 + b4) = hv;
            }
        }
        // stage X gate slice: xs[jw][g][b]
        {
            int b = tid >> 4, r = tid & 15, g = r >> 2, j2 = (r & 3) << 1;
            float2 xv = *(const float2*)(Xg + (size_t)(t * NB + b) * G4 + g * HH + blockIdx.x * 8 + j2);
            xs[j2 * 64 + g * 16 + b]       = xv.x;
            xs[(j2 + 1) * 64 + g * 16 + b] = xv.y;
        }
        __syncthreads();

        // ---- gate GEMV: acc[g][p] packs batches (2p, 2p+1) ----
        ull acc[4][8];
#pragma unroll
        for (int g = 0; g < 4; g++)
#pragma unroll
            for (int p = 0; p < 8; p++) acc[g][p] = 0ull;

        const float* wr = ws + wp * 4096;
#pragma unroll 8
        for (int i = 0; i < 32; i++) {
            int k = i * 32 + lane;
            ull W0 = pack2(wr[k]);
            ull W1 = pack2(wr[1024 + k]);
            ull W2 = pack2(wr[2048 + k]);
            ull W3 = pack2(wr[3072 + k]);
            const ulonglong2* hp = (const ulonglong2*)(hs + k * 20);
            ulonglong2 ha = hp[0], hb = hp[1], hc = hp[2], hd = hp[3];
            ffma2(acc[0][0], W0, ha.x); ffma2(acc[0][1], W0, ha.y);
            ffma2(acc[0][2], W0, hb.x); ffma2(acc[0][3], W0, hb.y);
            ffma2(acc[0][4], W0, hc.x); ffma2(acc[0][5], W0, hc.y);
            ffma2(acc[0][6], W0, hd.x); ffma2(acc[0][7], W0, hd.y);
            ffma2(acc[1][0], W1, ha.x); ffma2(acc[1][1], W1, ha.y);
            ffma2(acc[1][2], W1, hb.x); ffma2(acc[1][3], W1, hb.y);
            ffma2(acc[1][4], W1, hc.x); ffma2(acc[1][5], W1, hc.y);
            ffma2(acc[1][6], W1, hd.x); ffma2(acc[1][7], W1, hd.y);
            ffma2(acc[2][0], W2, ha.x); ffma2(acc[2][1], W2, ha.y);
            ffma2(acc[2][2], W2, hb.x); ffma2(acc[2][3], W2, hb.y);
            ffma2(acc[2][4], W2, hc.x); ffma2(acc[2][5], W2, hc.y);
            ffma2(acc[2][6], W2, hd.x); ffma2(acc[2][7], W2, hd.y);
            ffma2(acc[3][0], W3, ha.x); ffma2(acc[3][1], W3, ha.y);
            ffma2(acc[3][2], W3, hb.x); ffma2(acc[3][3], W3, hb.y);
            ffma2(acc[3][4], W3, hc.x); ffma2(acc[3][5], W3, hc.y);
            ffma2(acc[3][6], W3, hd.x); ffma2(acc[3][7], W3, hd.y);
        }

        // ---- multi-value butterfly reduction across lanes ----
        // v[q], q = g*8+p; after 5 stages lane l holds fully-summed q = l.
        ull* v = &acc[0][0];
#pragma unroll
        for (int m = 16; m >= 1; m >>= 1) {
            int half = m;   // live count halves each stage: 32->16->8->4->2->1
#pragma unroll
            for (int i = 0; i < 16; i++) {
                if (i < half) {
                    ull send = (lane & m) ? v[i] : v[i + half];
                    ull recv = __shfl_xor_sync(0xffffffffu, send, m);
                    ull keep = (lane & m) ? v[i + half] : v[i];
                    v[i] = fadd2(keep, recv);
                }
            }
        }
        {
            int g = lane >> 3, p = lane & 7;
            float lo, hi;
            unpack2(v[0], lo, hi);
            gs[wp * 64 + g * 16 + 2 * p]     = lo;
            gs[wp * 64 + g * 16 + 2 * p + 1] = hi;
        }
        __syncwarp();

        // ---- gate nonlinearity + state update ----
        if (lane < 16) {
            const int b = lane;
            float gi = gs[wp * 64 +  0 + b] + xs[wp * 64 +  0 + b];
            float gf = gs[wp * 64 + 16 + b] + xs[wp * 64 + 16 + b];
            float gg = gs[wp * 64 + 32 + b] + xs[wp * 64 + 32 + b];
            float go = gs[wp * 64 + 48 + b] + xs[wp * 64 + 48 + b];
            float c = sigf(gf) * creg + sigf(gi) * tanhf(gg);
            float h = sigf(go) * tanhf(c);
            creg = c;
            __stcg(&g_h[(t + 1) & 1][j * 16 + b], h);
            if (mode == 0)
                g_H0[(size_t)(t * NB + b) * HH + j] = h;
            else
                Out[(size_t)b * (LL * HH) + (size_t)t * HH + j] = h;
        }

        if (t != LL - 1) grid_sync();
    }
}

// ---------------------------------------------------------------------------
extern "C" void kernel_launch(void* const* d_in, const int* in_sizes, int n_in,
                              void* d_out, int out_size)
{
    const int*   x    = nullptr;
    const float* emb  = nullptr;
    const float* wih0 = nullptr;
    const float* bias_[2] = {nullptr, nullptr};
    const float* w4[3] = {nullptr, nullptr, nullptr};
    int nbias = 0, nw = 0;
    for (int i = 0; i < n_in; i++) {
        long long sz = in_sizes[i];
        if (sz == (long long)NB * LL)             x = (const int*)d_in[i];
        else if (sz == (long long)VV * EE)        emb = (const float*)d_in[i];
        else if (sz == (long long)G4 * EE)        wih0 = (const float*)d_in[i];
        else if (sz == (long long)G4)             { if (nbias < 2) bias_[nbias++] = (const float*)d_in[i]; }
        else if (sz == (long long)G4 * HH)        { if (nw < 3) w4[nw++] = (const float*)d_in[i]; }
    }
    if (!x || !emb || !wih0 || nbias < 2 || nw < 3) {
        x = (const int*)d_in[0];
        emb = (const float*)d_in[1];
        wih0 = (const float*)d_in[2];
        w4[0] = (const float*)d_in[3];
        bias_[0] = (const float*)d_in[4];
        w4[1] = (const float*)d_in[5];
        w4[2] = (const float*)d_in[6];
        bias_[1] = (const float*)d_in[7];
    }
    const float* whh0 = w4[0];
    const float* b0   = bias_[0];
    const float* wih1 = w4[1];
    const float* whh1 = w4[2];
    const float* b1   = bias_[1];
    float* out = (float*)d_out;

    const int smem_rec = (32768 + 20480 + 512 + 512) * (int)sizeof(float);  // 217088 B
    cudaFuncSetAttribute(lstm_rec, cudaFuncAttributeMaxDynamicSharedMemorySize, smem_rec);

    dim3 ggrid(G4 / 128, MM / 128);  // (32, 16)

    // Phase 1: X0 = emb[x] @ w_ih0^T + b0   (K = E = 512)
    gemm_nt<EE><<<ggrid, 256>>>(emb, x, wih0, b0, 0, 0);
    // Phase 2: layer-0 recurrence (persistent) -> g_H0
    lstm_rec<<<RB, 256, smem_rec>>>(whh0, out, 0, 0);
    // Phase 3: X1 = H0 @ w_ih1^T + b1       (K = H = 1024)
    gemm_nt<HH><<<ggrid, 256>>>(emb, nullptr, wih1, b1, 1, 1);
    // Phase 4: layer-1 recurrence -> out [N][L][H]
    lstm_rec<<<RB, 256, smem_rec>>>(whh1, out, 1, 1);
}

// round 9
// speedup vs baseline: 1.3445x; 1.0164x over previous
#include <cuda_runtime.h>

// Problem dims  (V, E, H, N, L = 32000, 512, 1024, 16, 128)
#define VV 32000
#define NB 16
#define LL 128
#define EE 512
#define HH 1024
#define G4 4096
#define MM (NB*LL)
#define RB 128           // persistent recurrence CTAs (1/SM, co-resident)

// Scratch
__device__ __align__(16) float g_X0[(size_t)MM * G4];   // 33.5 MB
__device__ __align__(16) float g_X1[(size_t)MM * G4];   // 33.5 MB
__device__ __align__(16) float g_H0[(size_t)MM * HH];   //  8.4 MB
__device__ __align__(16) float g_h[2][NB * HH];         // h double buffer, [k][b]
__device__ unsigned g_bar_arrive = 0;
__device__ unsigned g_bar_gen    = 0;

__device__ __forceinline__ float sigf(float x) { return 1.0f / (1.0f + __expf(-x)); }

// ---- packed f32x2 helpers -------------------------------------------------
typedef unsigned long long ull;

__device__ __forceinline__ ull pack2(float x) {
    ull r; asm("mov.b64 %0, {%1, %1};" : "=l"(r) : "f"(x)); return r;
}
__device__ __forceinline__ void ffma2(ull& d, ull a, ull b) {
    asm("fma.rn.f32x2 %0, %1, %2, %0;" : "+l"(d) : "l"(a), "l"(b));
}
__device__ __forceinline__ ull fadd2(ull a, ull b) {
    ull d; asm("add.rn.f32x2 %0, %1, %2;" : "=l"(d) : "l"(a), "l"(b)); return d;
}
__device__ __forceinline__ void unpack2(ull v, float& lo, float& hi) {
    asm("mov.b64 {%0, %1}, %2;" : "=f"(lo), "=f"(hi) : "l"(v));
}

// ---- grid-wide barrier: EXACT round-6 version (proven to pass) ------------
__device__ __forceinline__ void grid_sync() {
    __threadfence();
    __syncthreads();
    if (threadIdx.x == 0) {
        unsigned gen = ((volatile unsigned*)&g_bar_gen)[0];
        unsigned a = atomicAdd(&g_bar_arrive, 1u);
        if (a == RB - 1) {
            g_bar_arrive = 0;
            __threadfence();
            atomicExch(&g_bar_gen, gen + 1u);
        } else {
            while (((volatile unsigned*)&g_bar_gen)[0] == gen) { }
        }
        __threadfence();
    }
    __syncthreads();
}

// ---------------------------------------------------------------------------
// GEMM  C[m][r] = sum_k A[m][k]*B[r][k] + bias[r];  A gathered via tokens.
// Tile 128x128, 256 threads, 8x8/thread, K-tile 16, DOUBLE-BUFFERED smem.
// ---------------------------------------------------------------------------
template <int K>
__global__ __launch_bounds__(256) void gemm_nt(
    const float* __restrict__ Aext,
    const int*   __restrict__ tokens,
    const float* __restrict__ B,
    const float* __restrict__ bias,
    int a_sel, int c_sel)
{
    __shared__ __align__(16) float As[2][16][132];
    __shared__ __align__(16) float Bs[2][16][132];

    float* C = c_sel ? g_X1 : g_X0;
    const int bm = blockIdx.y, br = blockIdx.x;
    const int tid = threadIdx.x;
    const int tx = tid & 15, ty = tid >> 4;

    const int r0 = tid >> 2;
    const int r1 = r0 + 64;
    const int kq = (tid & 3) << 2;

    const float* arow0;
    const float* arow1;
    if (tokens) {
        int gm0 = bm * 128 + r0, gm1 = bm * 128 + r1;
        int t0 = tokens[(gm0 & (NB - 1)) * LL + (gm0 >> 4)];
        int t1 = tokens[(gm1 & (NB - 1)) * LL + (gm1 >> 4)];
        t0 = min(max(t0, 0), VV - 1);
        t1 = min(max(t1, 0), VV - 1);
        arow0 = Aext + (size_t)t0 * K;
        arow1 = Aext + (size_t)t1 * K;
    } else {
        const float* A = a_sel ? g_H0 : Aext;
        arow0 = A + (size_t)(bm * 128 + r0) * K;
        arow1 = A + (size_t)(bm * 128 + r1) * K;
    }
    const float* brow0 = B + (size_t)(br * 128 + r0) * K;
    const float* brow1 = B + (size_t)(br * 128 + r1) * K;

    float acc[8][8];
#pragma unroll
    for (int i = 0; i < 8; i++)
#pragma unroll
        for (int jj = 0; jj < 8; jj++) acc[i][jj] = 0.0f;

    // prologue: tile 0
    {
        float4 av0 = *(const float4*)(arow0 + kq);
        float4 av1 = *(const float4*)(arow1 + kq);
        float4 bv0 = *(const float4*)(brow0 + kq);
        float4 bv1 = *(const float4*)(brow1 + kq);
        As[0][kq + 0][r0] = av0.x; As[0][kq + 1][r0] = av0.y; As[0][kq + 2][r0] = av0.z; As[0][kq + 3][r0] = av0.w;
        As[0][kq + 0][r1] = av1.x; As[0][kq + 1][r1] = av1.y; As[0][kq + 2][r1] = av1.z; As[0][kq + 3][r1] = av1.w;
        Bs[0][kq + 0][r0] = bv0.x; Bs[0][kq + 1][r0] = bv0.y; Bs[0][kq + 2][r0] = bv0.z; Bs[0][kq + 3][r0] = bv0.w;
        Bs[0][kq + 0][r1] = bv1.x; Bs[0][kq + 1][r1] = bv1.y; Bs[0][kq + 2][r1] = bv1.z; Bs[0][kq + 3][r1] = bv1.w;
    }
    __syncthreads();

    int cur = 0;
#pragma unroll 1
    for (int k0 = 0; k0 < K; k0 += 16) {
        const bool more = (k0 + 16) < K;
        float4 nav0, nav1, nbv0, nbv1;
        if (more) {                       // issue next tile's LDGs early
            nav0 = *(const float4*)(arow0 + k0 + 16 + kq);
            nav1 = *(const float4*)(arow1 + k0 + 16 + kq);
            nbv0 = *(const float4*)(brow0 + k0 + 16 + kq);
            nbv1 = *(const float4*)(brow1 + k0 + 16 + kq);
        }

#pragma unroll
        for (int kk = 0; kk < 16; kk++) {
            float4 a0 = *(const float4*)&As[cur][kk][ty * 8];
            float4 a1 = *(const float4*)&As[cur][kk][ty * 8 + 4];
            float4 b0 = *(const float4*)&Bs[cur][kk][tx * 8];
            float4 b1 = *(const float4*)&Bs[cur][kk][tx * 8 + 4];
            float a[8] = {a0.x, a0.y, a0.z, a0.w, a1.x, a1.y, a1.z, a1.w};
            float b[8] = {b0.x, b0.y, b0.z, b0.w, b1.x, b1.y, b1.z, b1.w};
#pragma unroll
            for (int i = 0; i < 8; i++)
#pragma unroll
                for (int jj = 0; jj < 8; jj++)
                    acc[i][jj] = fmaf(a[i], b[jj], acc[i][jj]);
        }

        if (more) {
            int nxt = cur ^ 1;
            As[nxt][kq + 0][r0] = nav0.x; As[nxt][kq + 1][r0] = nav0.y; As[nxt][kq + 2][r0] = nav0.z; As[nxt][kq + 3][r0] = nav0.w;
            As[nxt][kq + 0][r1] = nav1.x; As[nxt][kq + 1][r1] = nav1.y; As[nxt][kq + 2][r1] = nav1.z; As[nxt][kq + 3][r1] = nav1.w;
            Bs[nxt][kq + 0][r0] = nbv0.x; Bs[nxt][kq + 1][r0] = nbv0.y; Bs[nxt][kq + 2][r0] = nbv0.z; Bs[nxt][kq + 3][r0] = nbv0.w;
            Bs[nxt][kq + 0][r1] = nbv1.x; Bs[nxt][kq + 1][r1] = nbv1.y; Bs[nxt][kq + 2][r1] = nbv1.z; Bs[nxt][kq + 3][r1] = nbv1.w;
            __syncthreads();
            cur = nxt;
        }
    }

    const int gc = br * 128 + tx * 8;
    float bia[8];
#pragma unroll
    for (int jj = 0; jj < 8; jj++) bia[jj] = bias[gc + jj];
#pragma unroll
    for (int i = 0; i < 8; i++) {
        int gm = bm * 128 + ty * 8 + i;
        float4 o0, o1;
        o0.x = acc[i][0] + bia[0]; o0.y = acc[i][1] + bia[1];
        o0.z = acc[i][2] + bia[2]; o0.w = acc[i][3] + bia[3];
        o1.x = acc[i][4] + bia[4]; o1.y = acc[i][5] + bia[5];
        o1.z = acc[i][6] + bia[6]; o1.w = acc[i][7] + bia[7];
        *(float4*)(C + (size_t)gm * G4 + gc)     = o0;
        *(float4*)(C + (size_t)gm * G4 + gc + 4) = o1;
    }
}

// ---------------------------------------------------------------------------
// Persistent LSTM recurrence: 128 CTAs x 256 thr, all 128 steps in one launch.
// ---------------------------------------------------------------------------
__global__ __launch_bounds__(256) void lstm_rec(
    const float* __restrict__ Whh,
    float* __restrict__ Out,
    int xsel, int mode)
{
    extern __shared__ __align__(16) float sm[];
    float* ws = sm;                    // 32768 floats: ws[w][g][k]
    float* hs = sm + 32768;            // 20480 floats: h padded [k][20]
    float* gs = hs + 20480;            // 512: reduced gates
    float* xs = gs + 512;              // 512: staged X slice

    const float* Xg = xsel ? g_X1 : g_X0;
    const int tid = threadIdx.x, lane = tid & 31, wp = tid >> 5;
    const int j = blockIdx.x * 8 + wp;

    // ---- preload weight slice (128 KB) into smem ----
    for (int i = tid; i < 8192; i += 256) {
        int wgk = i * 4;
        int w_ = wgk >> 12, g = (wgk >> 10) & 3, k = wgk & 1023;
        ((float4*)ws)[i] = *(const float4*)(Whh + (size_t)(g * HH + blockIdx.x * 8 + w_) * HH + k);
    }
    for (int i = tid; i < 20480; i += 256) hs[i] = 0.0f;

    float creg = 0.0f;
    __syncthreads();

    for (int t = 0; t < LL; t++) {
        // prefetch X gate slice early (latency overlaps h staging)
        float2 xv;
        int xb = tid >> 4, xr = tid & 15, xg = xr >> 2, xj2 = (xr & 3) << 1;
        xv = *(const float2*)(Xg + (size_t)(t * NB + xb) * G4 + xg * HH + blockIdx.x * 8 + xj2);

        if (t > 0) {
            const float4* src = (const float4*)g_h[t & 1];
            for (int i = tid; i < 4096; i += 256) {
                float4 hv = __ldcg(src + i);
                int k = i >> 2, b4 = (i & 3) << 2;
                *(float4*)(hs + k * 20 + b4) = hv;
            }
        }
        xs[xj2 * 64 + xg * 16 + xb]       = xv.x;
        xs[(xj2 + 1) * 64 + xg * 16 + xb] = xv.y;
        __syncthreads();

        // ---- gate GEMV: acc[g][p] packs batches (2p, 2p+1) ----
        ull acc[4][8];
#pragma unroll
        for (int g = 0; g < 4; g++)
#pragma unroll
            for (int p = 0; p < 8; p++) acc[g][p] = 0ull;

        const float* wr = ws + wp * 4096;
#pragma unroll 8
        for (int i = 0; i < 32; i++) {
            int k = i * 32 + lane;
            ull W0 = pack2(wr[k]);
            ull W1 = pack2(wr[1024 + k]);
            ull W2 = pack2(wr[2048 + k]);
            ull W3 = pack2(wr[3072 + k]);
            const ulonglong2* hp = (const ulonglong2*)(hs + k * 20);
            ulonglong2 ha = hp[0], hb = hp[1], hc = hp[2], hd = hp[3];
            ffma2(acc[0][0], W0, ha.x); ffma2(acc[0][1], W0, ha.y);
            ffma2(acc[0][2], W0, hb.x); ffma2(acc[0][3], W0, hb.y);
            ffma2(acc[0][4], W0, hc.x); ffma2(acc[0][5], W0, hc.y);
            ffma2(acc[0][6], W0, hd.x); ffma2(acc[0][7], W0, hd.y);
            ffma2(acc[1][0], W1, ha.x); ffma2(acc[1][1], W1, ha.y);
            ffma2(acc[1][2], W1, hb.x); ffma2(acc[1][3], W1, hb.y);
            ffma2(acc[1][4], W1, hc.x); ffma2(acc[1][5], W1, hc.y);
            ffma2(acc[1][6], W1, hd.x); ffma2(acc[1][7], W1, hd.y);
            ffma2(acc[2][0], W2, ha.x); ffma2(acc[2][1], W2, ha.y);
            ffma2(acc[2][2], W2, hb.x); ffma2(acc[2][3], W2, hb.y);
            ffma2(acc[2][4], W2, hc.x); ffma2(acc[2][5], W2, hc.y);
            ffma2(acc[2][6], W2, hd.x); ffma2(acc[2][7], W2, hd.y);
            ffma2(acc[3][0], W3, ha.x); ffma2(acc[3][1], W3, ha.y);
            ffma2(acc[3][2], W3, hb.x); ffma2(acc[3][3], W3, hb.y);
            ffma2(acc[3][4], W3, hc.x); ffma2(acc[3][5], W3, hc.y);
            ffma2(acc[3][6], W3, hd.x); ffma2(acc[3][7], W3, hd.y);
        }

        // ---- multi-value butterfly reduction across lanes ----
        ull* v = &acc[0][0];
#pragma unroll
        for (int m = 16; m >= 1; m >>= 1) {
            int half = m;
#pragma unroll
            for (int i = 0; i < 16; i++) {
                if (i < half) {
                    ull send = (lane & m) ? v[i] : v[i + half];
                    ull recv = __shfl_xor_sync(0xffffffffu, send, m);
                    ull keep = (lane & m) ? v[i + half] : v[i];
                    v[i] = fadd2(keep, recv);
                }
            }
        }
        {
            int g = lane >> 3, p = lane & 7;
            float lo, hi;
            unpack2(v[0], lo, hi);
            gs[wp * 64 + g * 16 + 2 * p]     = lo;
            gs[wp * 64 + g * 16 + 2 * p + 1] = hi;
        }
        __syncwarp();

        if (lane < 16) {
            const int b = lane;
            float gi = gs[wp * 64 +  0 + b] + xs[wp * 64 +  0 + b];
            float gf = gs[wp * 64 + 16 + b] + xs[wp * 64 + 16 + b];
            float gg = gs[wp * 64 + 32 + b] + xs[wp * 64 + 32 + b];
            float go = gs[wp * 64 + 48 + b] + xs[wp * 64 + 48 + b];
            float c = sigf(gf) * creg + sigf(gi) * tanhf(gg);
            float h = sigf(go) * tanhf(c);
            creg = c;
            __stcg(&g_h[(t + 1) & 1][j * 16 + b], h);
            if (mode == 0)
                g_H0[(size_t)(t * NB + b) * HH + j] = h;
            else
                Out[(size_t)b * (LL * HH) + (size_t)t * HH + j] = h;
        }

        if (t != LL - 1) grid_sync();
    }
}

// ---------------------------------------------------------------------------
extern "C" void kernel_launch(void* const* d_in, const int* in_sizes, int n_in,
                              void* d_out, int out_size)
{
    const int*   x    = nullptr;
    const float* emb  = nullptr;
    const float* wih0 = nullptr;
    const float* bias_[2] = {nullptr, nullptr};
    const float* w4[3] = {nullptr, nullptr, nullptr};
    int nbias = 0, nw = 0;
    for (int i = 0; i < n_in; i++) {
        long long sz = in_sizes[i];
        if (sz == (long long)NB * LL)             x = (const int*)d_in[i];
        else if (sz == (long long)VV * EE)        emb = (const float*)d_in[i];
        else if (sz == (long long)G4 * EE)        wih0 = (const float*)d_in[i];
        else if (sz == (long long)G4)             { if (nbias < 2) bias_[nbias++] = (const float*)d_in[i]; }
        else if (sz == (long long)G4 * HH)        { if (nw < 3) w4[nw++] = (const float*)d_in[i]; }
    }
    if (!x || !emb || !wih0 || nbias < 2 || nw < 3) {
        x = (const int*)d_in[0];
        emb = (const float*)d_in[1];
        wih0 = (const float*)d_in[2];
        w4[0] = (const float*)d_in[3];
        bias_[0] = (const float*)d_in[4];
        w4[1] = (const float*)d_in[5];
        w4[2] = (const float*)d_in[6];
        bias_[1] = (const float*)d_in[7];
    }
    const float* whh0 = w4[0];
    const float* b0   = bias_[0];
    const float* wih1 = w4[1];
    const float* whh1 = w4[2];
    const float* b1   = bias_[1];
    float* out = (float*)d_out;

    const int smem_rec = (32768 + 20480 + 512 + 512) * (int)sizeof(float);  // 217088 B
    cudaFuncSetAttribute(lstm_rec, cudaFuncAttributeMaxDynamicSharedMemorySize, smem_rec);

    dim3 ggrid(G4 / 128, MM / 128);  // (32, 16)

    gemm_nt<EE><<<ggrid, 256>>>(emb, x, wih0, b0, 0, 0);
    lstm_rec<<<RB, 256, smem_rec>>>(whh0, out, 0, 0);
    gemm_nt<HH><<<ggrid, 256>>>(emb, nullptr, wih1, b1, 1, 1);
    lstm_rec<<<RB, 256, smem_rec>>>(whh1, out, 1, 1);
}